// round 2
// baseline (speedup 1.0000x reference)
#include <cuda_runtime.h>
#include <cuda_bf16.h>

#define NN   100000
#define EE   1600000
#define INCH 128
#define C1   128
#define HID  64
#define HALF (NN/2)

// ---------------- scratch (device globals; allocation-free) ----------------
__device__ float g_xw[(size_t)NN * 128];   // xw' = (x@W)*dinv[row]  (layer2 uses first NN*64)
__device__ float g_acc[(size_t)NN * 128];  // scatter accumulator (layer2 uses first NN*64)
__device__ float g_h[(size_t)NN * 128];    // layer-1 activations
__device__ float g_deg1[NN], g_deg2[NN], g_dinv1[NN], g_dinv2[NN];

// ---------------- packed f32x2 helpers (sm_103a FFMA2) ----------------
__device__ __forceinline__ unsigned long long pack_dup(float a) {
    unsigned long long r;
    asm("mov.b64 %0, {%1, %1};" : "=l"(r) : "r"(__float_as_uint(a)));
    return r;
}
__device__ __forceinline__ unsigned long long pack2f(float2 v) {
    unsigned long long r;
    asm("mov.b64 %0, {%1, %2};" : "=l"(r) : "r"(__float_as_uint(v.x)), "r"(__float_as_uint(v.y)));
    return r;
}
__device__ __forceinline__ float2 unpack2(unsigned long long v) {
    unsigned int lo, hi;
    asm("mov.b64 {%0, %1}, %2;" : "=r"(lo), "=r"(hi) : "l"(v));
    return make_float2(__uint_as_float(lo), __uint_as_float(hi));
}
__device__ __forceinline__ void fma2(unsigned long long& d, unsigned long long a, unsigned long long b) {
    asm("fma.rn.f32x2 %0, %1, %2, %0;" : "+l"(d) : "l"(a), "l"(b));
}

// ---------------- degree / dinv ----------------
__global__ void k_initdeg() {
    int i = blockIdx.x * 256 + threadIdx.x;
    if (i < NN) { g_deg1[i] = 1.0f; g_deg2[i] = 1.0f; }  // self-loop weight 1
}
__global__ void k_deg(const int* __restrict__ ei,
                      const float* __restrict__ w,
                      const int* __restrict__ et) {
    int e = blockIdx.x * 256 + threadIdx.x;
    if (e < EE) {
        int dst = ei[EE + e];
        atomicAdd(&g_deg1[dst], w[e]);
        atomicAdd(&g_deg2[dst], (float)et[e]);
    }
}
__global__ void k_dinv() {
    int i = blockIdx.x * 256 + threadIdx.x;
    if (i < NN) {
        float d1 = g_deg1[i], d2 = g_deg2[i];
        g_dinv1[i] = (d1 > 0.f) ? rsqrtf(d1) : 0.f;
        g_dinv2[i] = (d2 > 0.f) ? rsqrtf(d2) : 0.f;
    }
}

// ---------------- GEMM1: xw' = (x @ W1) * dinv1[row]; also init acc (self loop) ----------------
// 256 threads, 64-row tile. W1 (128x128) in smem, x tile stored k-major (stride 66).
// Thread: 8 rows (4 row-pairs via f32x2) x 4 cols.
__global__ void k_gemm1(const float* __restrict__ x, const float* __restrict__ W) {
    extern __shared__ float sm[];
    float* Ws = sm;              // 128*128
    float* Xs = sm + 128 * 128;  // 128 * 66
    const int tid = threadIdx.x;
    const int rbase = blockIdx.x * 64;

    const float4* W4 = (const float4*)W;
    float4* Ws4 = (float4*)Ws;
#pragma unroll
    for (int i = 0; i < 16; i++) Ws4[i * 256 + tid] = W4[i * 256 + tid];

#pragma unroll
    for (int it = 0; it < 32; it++) {
        int idx = it * 256 + tid;           // 64*128 elements
        int r = idx >> 7, k = idx & 127;
        int row = rbase + r;
        Xs[k * 66 + r] = (row < NN) ? x[(size_t)row * 128 + k] : 0.f;
    }
    __syncthreads();

    const int tx = tid & 31, ty = tid >> 5;
    const int cb = tx * 4, rb = ty * 8;
    unsigned long long acc[4][4];
#pragma unroll
    for (int p = 0; p < 4; p++)
#pragma unroll
        for (int c = 0; c < 4; c++) acc[p][c] = 0ull;

#pragma unroll 4
    for (int k = 0; k < 128; k++) {
        float4 w4 = *(const float4*)(Ws + k * 128 + cb);
        unsigned long long wd0 = pack_dup(w4.x), wd1 = pack_dup(w4.y),
                           wd2 = pack_dup(w4.z), wd3 = pack_dup(w4.w);
        const float* xrow = Xs + k * 66 + rb;
#pragma unroll
        for (int p = 0; p < 4; p++) {
            float2 af = *(const float2*)(xrow + 2 * p);   // (row 2p, row 2p+1)
            unsigned long long a2 = pack2f(af);
            fma2(acc[p][0], a2, wd0);
            fma2(acc[p][1], a2, wd1);
            fma2(acc[p][2], a2, wd2);
            fma2(acc[p][3], a2, wd3);
        }
    }

#pragma unroll
    for (int p = 0; p < 4; p++) {
        float2 c0 = unpack2(acc[p][0]), c1 = unpack2(acc[p][1]),
               c2 = unpack2(acc[p][2]), c3 = unpack2(acc[p][3]);
        int row0 = rbase + rb + 2 * p;
        if (row0 < NN) {
            float s = g_dinv1[row0];
            float4 o = make_float4(c0.x * s, c1.x * s, c2.x * s, c3.x * s);
            *(float4*)&g_xw[(size_t)row0 * 128 + cb] = o;
            *(float4*)&g_acc[(size_t)row0 * 128 + cb] = o;
        }
        int row1 = row0 + 1;
        if (row1 < NN) {
            float s = g_dinv1[row1];
            float4 o = make_float4(c0.y * s, c1.y * s, c2.y * s, c3.y * s);
            *(float4*)&g_xw[(size_t)row1 * 128 + cb] = o;
            *(float4*)&g_acc[(size_t)row1 * 128 + cb] = o;
        }
    }
}

// ---------------- GEMM2: xw2' = (h @ W2) * dinv2[row]; also init acc ----------------
// 256 threads, 64-row x 64-col tile. Thread: 4 rows (2 pairs) x 4 cols.
__global__ void k_gemm2(const float* __restrict__ W) {
    extern __shared__ float sm[];
    float* Ws = sm;              // 128*64
    float* Xs = sm + 128 * 64;   // 128 * 66
    const int tid = threadIdx.x;
    const int rbase = blockIdx.x * 64;

    const float4* W4 = (const float4*)W;
    float4* Ws4 = (float4*)Ws;
#pragma unroll
    for (int i = 0; i < 8; i++) Ws4[i * 256 + tid] = W4[i * 256 + tid];

#pragma unroll
    for (int it = 0; it < 32; it++) {
        int idx = it * 256 + tid;
        int r = idx >> 7, k = idx & 127;
        int row = rbase + r;
        Xs[k * 66 + r] = (row < NN) ? g_h[(size_t)row * 128 + k] : 0.f;
    }
    __syncthreads();

    const int tx = tid & 15, ty = tid >> 4;
    const int cb = tx * 4, rb = ty * 4;
    unsigned long long acc[2][4];
#pragma unroll
    for (int p = 0; p < 2; p++)
#pragma unroll
        for (int c = 0; c < 4; c++) acc[p][c] = 0ull;

#pragma unroll 4
    for (int k = 0; k < 128; k++) {
        float4 w4 = *(const float4*)(Ws + k * 64 + cb);
        unsigned long long wd0 = pack_dup(w4.x), wd1 = pack_dup(w4.y),
                           wd2 = pack_dup(w4.z), wd3 = pack_dup(w4.w);
        const float* xrow = Xs + k * 66 + rb;
#pragma unroll
        for (int p = 0; p < 2; p++) {
            float2 af = *(const float2*)(xrow + 2 * p);
            unsigned long long a2 = pack2f(af);
            fma2(acc[p][0], a2, wd0);
            fma2(acc[p][1], a2, wd1);
            fma2(acc[p][2], a2, wd2);
            fma2(acc[p][3], a2, wd3);
        }
    }

#pragma unroll
    for (int p = 0; p < 2; p++) {
        float2 c0 = unpack2(acc[p][0]), c1 = unpack2(acc[p][1]),
               c2 = unpack2(acc[p][2]), c3 = unpack2(acc[p][3]);
        int row0 = rbase + rb + 2 * p;
        if (row0 < NN) {
            float s = g_dinv2[row0];
            float4 o = make_float4(c0.x * s, c1.x * s, c2.x * s, c3.x * s);
            *(float4*)&g_xw[(size_t)row0 * 64 + cb] = o;
            *(float4*)&g_acc[(size_t)row0 * 64 + cb] = o;
        }
        int row1 = row0 + 1;
        if (row1 < NN) {
            float s = g_dinv2[row1];
            float4 o = make_float4(c0.y * s, c1.y * s, c2.y * s, c3.y * s);
            *(float4*)&g_xw[(size_t)row1 * 64 + cb] = o;
            *(float4*)&g_acc[(size_t)row1 * 64 + cb] = o;
        }
    }
}

// ---------------- scatter layer 1: one warp per edge, 128 ch ----------------
__global__ void k_scatter1(const int* __restrict__ ei, const float* __restrict__ w) {
    int gid = blockIdx.x * 256 + threadIdx.x;   // exactly EE*32 threads
    int e = gid >> 5;
    int lane = gid & 31;
    int src = 0, dst = 0; float ww = 0.f;
    if (lane == 0) { src = ei[e]; dst = ei[EE + e]; ww = w[e]; }
    src = __shfl_sync(0xffffffffu, src, 0);
    dst = __shfl_sync(0xffffffffu, dst, 0);
    ww  = __shfl_sync(0xffffffffu, ww, 0);
    float4 v = *(const float4*)&g_xw[(size_t)src * 128 + lane * 4];
    v.x *= ww; v.y *= ww; v.z *= ww; v.w *= ww;
    float* p = &g_acc[(size_t)dst * 128 + lane * 4];
    asm volatile("red.global.add.v4.f32 [%0], {%1, %2, %3, %4};"
                 :: "l"(p), "f"(v.x), "f"(v.y), "f"(v.z), "f"(v.w) : "memory");
}

// ---------------- finalize layer 1: h = prelu(acc*dinv1 + b1, a1) ----------------
__global__ void k_fin1(const float* __restrict__ b, const float* __restrict__ al) {
    int gid = blockIdx.x * 256 + threadIdx.x;    // NN*32 threads exactly
    int row = gid >> 5, q = gid & 31;
    float s = g_dinv1[row];
    float4 v = *(const float4*)&g_acc[(size_t)row * 128 + q * 4];
    float4 bb = *(const float4*)&b[q * 4];
    float4 aa = *(const float4*)&al[q * 4];
    v.x = v.x * s + bb.x; v.y = v.y * s + bb.y; v.z = v.z * s + bb.z; v.w = v.w * s + bb.w;
    v.x = (v.x >= 0.f) ? v.x : aa.x * v.x;
    v.y = (v.y >= 0.f) ? v.y : aa.y * v.y;
    v.z = (v.z >= 0.f) ? v.z : aa.z * v.z;
    v.w = (v.w >= 0.f) ? v.w : aa.w * v.w;
    *(float4*)&g_h[(size_t)row * 128 + q * 4] = v;
}

// ---------------- scatter layer 2: 16 lanes per edge, 64 ch ----------------
__global__ void k_scatter2(const int* __restrict__ ei, const int* __restrict__ et) {
    int gid = blockIdx.x * 256 + threadIdx.x;   // exactly EE*16 threads
    int e = gid >> 4;
    int lane = gid & 15;
    int src = 0, dst = 0; float ww = 0.f;
    if (lane == 0) { src = ei[e]; dst = ei[EE + e]; ww = (float)et[e]; }
    src = __shfl_sync(0xffffffffu, src, 0, 16);
    dst = __shfl_sync(0xffffffffu, dst, 0, 16);
    ww  = __shfl_sync(0xffffffffu, ww, 0, 16);
    float4 v = *(const float4*)&g_xw[(size_t)src * 64 + lane * 4];
    v.x *= ww; v.y *= ww; v.z *= ww; v.w *= ww;
    float* p = &g_acc[(size_t)dst * 64 + lane * 4];
    asm volatile("red.global.add.v4.f32 [%0], {%1, %2, %3, %4};"
                 :: "l"(p), "f"(v.x), "f"(v.y), "f"(v.z), "f"(v.w) : "memory");
}

// ---------------- finalize layer 2 + half-combine ----------------
__global__ void k_final(const float* __restrict__ b, const float* __restrict__ al,
                        float* __restrict__ out) {
    int gid = blockIdx.x * 256 + threadIdx.x;   // HALF*16 threads exactly
    int i = gid >> 4, q = gid & 15;
    int c = q * 4;
    float4 bb = *(const float4*)&b[c];
    float4 aa = *(const float4*)&al[c];

    float sA = g_dinv2[i];
    float4 va = *(const float4*)&g_acc[(size_t)i * 64 + c];
    va.x = va.x * sA + bb.x; va.y = va.y * sA + bb.y; va.z = va.z * sA + bb.z; va.w = va.w * sA + bb.w;
    va.x = (va.x >= 0.f) ? va.x : aa.x * va.x;
    va.y = (va.y >= 0.f) ? va.y : aa.y * va.y;
    va.z = (va.z >= 0.f) ? va.z : aa.z * va.z;
    va.w = (va.w >= 0.f) ? va.w : aa.w * va.w;

    int j = i + HALF;
    float sB = g_dinv2[j];
    float4 vb = *(const float4*)&g_acc[(size_t)j * 64 + c];
    vb.x = vb.x * sB + bb.x; vb.y = vb.y * sB + bb.y; vb.z = vb.z * sB + bb.z; vb.w = vb.w * sB + bb.w;
    vb.x = (vb.x >= 0.f) ? vb.x : aa.x * vb.x;
    vb.y = (vb.y >= 0.f) ? vb.y : aa.y * vb.y;
    vb.z = (vb.z >= 0.f) ? vb.z : aa.z * vb.z;
    vb.w = (vb.w >= 0.f) ? vb.w : aa.w * vb.w;

    float4 o = make_float4(0.5f * (va.x + vb.x), 0.5f * (va.y + vb.y),
                           0.5f * (va.z + vb.z), 0.5f * (va.w + vb.w));
    *(float4*)&out[(size_t)i * 64 + c] = o;
}

// ---------------- launch ----------------
extern "C" void kernel_launch(void* const* d_in, const int* in_sizes, int n_in,
                              void* d_out, int out_size) {
    (void)in_sizes; (void)n_in; (void)out_size;
    const float* x   = (const float*)d_in[0];
    const int*   ei  = (const int*)d_in[1];
    const float* ew  = (const float*)d_in[2];
    const int*   et  = (const int*)d_in[3];
    const float* W1  = (const float*)d_in[4];
    const float* b1  = (const float*)d_in[5];
    const float* a1  = (const float*)d_in[6];
    const float* W2  = (const float*)d_in[7];
    const float* b2  = (const float*)d_in[8];
    const float* a2  = (const float*)d_in[9];
    float* out = (float*)d_out;

    const int smem1 = (128 * 128 + 128 * 66) * sizeof(float);   // 99328
    const int smem2 = (128 * 64  + 128 * 66) * sizeof(float);   // 66560
    cudaFuncSetAttribute(k_gemm1, cudaFuncAttributeMaxDynamicSharedMemorySize, smem1);
    cudaFuncSetAttribute(k_gemm2, cudaFuncAttributeMaxDynamicSharedMemorySize, smem2);

    const int gemm_blocks = (NN + 63) / 64;   // 1563

    k_initdeg<<<(NN + 255) / 256, 256>>>();
    k_deg<<<(EE + 255) / 256, 256>>>(ei, ew, et);
    k_dinv<<<(NN + 255) / 256, 256>>>();

    // layer 1
    k_gemm1<<<gemm_blocks, 256, smem1>>>(x, W1);
    k_scatter1<<<EE * 32 / 256, 256>>>(ei, ew);
    k_fin1<<<NN * 32 / 256, 256>>>(b1, a1);

    // layer 2
    k_gemm2<<<gemm_blocks, 256, smem2>>>(W2);
    k_scatter2<<<EE * 16 / 256, 256>>>(ei, et);
    k_final<<<HALF * 16 / 256, 256>>>(b2, a2, out);
}

// round 3
// speedup vs baseline: 1.0059x; 1.0059x over previous
#include <cuda_runtime.h>
#include <cuda_bf16.h>

#define NN   100000
#define EE   1600000
#define HALF (NN/2)

// ---------------- scratch (device globals; allocation-free) ----------------
__device__ float g_xw[(size_t)NN * 128];   // (x@W)*dinv[row]  (layer2 uses first NN*64)
__device__ float g_h[(size_t)NN * 128];    // layer-1 activations
__device__ float g_h2[(size_t)NN * 64];    // layer-2 activations (pre-combine)
__device__ float g_deg1[NN], g_deg2[NN], g_dinv1[NN], g_dinv2[NN];
__device__ int   g_hist[NN];
__device__ int   g_off[NN + 1];
__device__ int   g_cur[NN];
__device__ int2  g_e1[EE];                 // (src, w1 bits) sorted by dst
__device__ int2  g_e2[EE];                 // (src, w2 bits) sorted by dst

// ---------------- packed f32x2 helpers (sm_103a FFMA2) ----------------
__device__ __forceinline__ unsigned long long pack_dup(float a) {
    unsigned long long r;
    asm("mov.b64 %0, {%1, %1};" : "=l"(r) : "r"(__float_as_uint(a)));
    return r;
}
__device__ __forceinline__ unsigned long long pack2f(float2 v) {
    unsigned long long r;
    asm("mov.b64 %0, {%1, %2};" : "=l"(r) : "r"(__float_as_uint(v.x)), "r"(__float_as_uint(v.y)));
    return r;
}
__device__ __forceinline__ float2 unpack2(unsigned long long v) {
    unsigned int lo, hi;
    asm("mov.b64 {%0, %1}, %2;" : "=r"(lo), "=r"(hi) : "l"(v));
    return make_float2(__uint_as_float(lo), __uint_as_float(hi));
}
__device__ __forceinline__ void fma2(unsigned long long& d, unsigned long long a, unsigned long long b) {
    asm("fma.rn.f32x2 %0, %1, %2, %0;" : "+l"(d) : "l"(a), "l"(b));
}

// ---------------- CSR build ----------------
__global__ void k_init() {
    int i = blockIdx.x * 256 + threadIdx.x;
    if (i < NN) { g_hist[i] = 0; g_deg1[i] = 1.0f; g_deg2[i] = 1.0f; }
}
__global__ void k_hist(const int* __restrict__ ei, const float* __restrict__ w,
                       const int* __restrict__ et) {
    int e = blockIdx.x * 256 + threadIdx.x;
    if (e < EE) {
        int dst = ei[EE + e];
        atomicAdd(&g_hist[dst], 1);
        atomicAdd(&g_deg1[dst], w[e]);
        atomicAdd(&g_deg2[dst], (float)et[e]);
    }
}
__global__ void k_dinv() {
    int i = blockIdx.x * 256 + threadIdx.x;
    if (i < NN) {
        float d1 = g_deg1[i], d2 = g_deg2[i];
        g_dinv1[i] = (d1 > 0.f) ? rsqrtf(d1) : 0.f;
        g_dinv2[i] = (d2 > 0.f) ? rsqrtf(d2) : 0.f;
    }
}
// exclusive scan of g_hist -> g_off, g_cur. One block, 1024 threads.
__global__ void k_scan() {
    __shared__ int ssum[1024];
    const int t = threadIdx.x;
    const int CH = (NN + 1023) / 1024;     // 98
    int beg = t * CH, end = min(beg + CH, NN);
    int s = 0;
    for (int i = beg; i < end; i++) s += g_hist[i];
    ssum[t] = s;
    __syncthreads();
    for (int off = 1; off < 1024; off <<= 1) {
        int v = (t >= off) ? ssum[t - off] : 0;
        __syncthreads();
        if (t >= off) ssum[t] += v;
        __syncthreads();
    }
    int run = (t > 0) ? ssum[t - 1] : 0;   // exclusive
    for (int i = beg; i < end; i++) {
        g_off[i] = run; g_cur[i] = run;
        run += g_hist[i];
    }
    if (t == 1023) g_off[NN] = run;
}
__global__ void k_fill(const int* __restrict__ ei, const float* __restrict__ w,
                       const int* __restrict__ et) {
    int e = blockIdx.x * 256 + threadIdx.x;
    if (e < EE) {
        int src = ei[e];
        int dst = ei[EE + e];
        int pos = atomicAdd(&g_cur[dst], 1);
        g_e1[pos] = make_int2(src, __float_as_int(w[e]));
        g_e2[pos] = make_int2(src, __float_as_int((float)et[e]));
    }
}

// ---------------- GEMM1: g_xw = (x @ W1) * dinv1[row] ----------------
__global__ void k_gemm1(const float* __restrict__ x, const float* __restrict__ W) {
    extern __shared__ float sm[];
    float* Ws = sm;              // 128*128
    float* Xs = sm + 128 * 128;  // 128 * 66
    const int tid = threadIdx.x;
    const int rbase = blockIdx.x * 64;

    const float4* W4 = (const float4*)W;
    float4* Ws4 = (float4*)Ws;
#pragma unroll
    for (int i = 0; i < 16; i++) Ws4[i * 256 + tid] = W4[i * 256 + tid];

#pragma unroll
    for (int it = 0; it < 32; it++) {
        int idx = it * 256 + tid;
        int r = idx >> 7, k = idx & 127;
        int row = rbase + r;
        Xs[k * 66 + r] = (row < NN) ? x[(size_t)row * 128 + k] : 0.f;
    }
    __syncthreads();

    const int tx = tid & 31, ty = tid >> 5;
    const int cb = tx * 4, rb = ty * 8;
    unsigned long long acc[4][4];
#pragma unroll
    for (int p = 0; p < 4; p++)
#pragma unroll
        for (int c = 0; c < 4; c++) acc[p][c] = 0ull;

#pragma unroll 4
    for (int k = 0; k < 128; k++) {
        float4 w4 = *(const float4*)(Ws + k * 128 + cb);
        unsigned long long wd0 = pack_dup(w4.x), wd1 = pack_dup(w4.y),
                           wd2 = pack_dup(w4.z), wd3 = pack_dup(w4.w);
        const float* xrow = Xs + k * 66 + rb;
#pragma unroll
        for (int p = 0; p < 4; p++) {
            unsigned long long a2 = pack2f(*(const float2*)(xrow + 2 * p));
            fma2(acc[p][0], a2, wd0);
            fma2(acc[p][1], a2, wd1);
            fma2(acc[p][2], a2, wd2);
            fma2(acc[p][3], a2, wd3);
        }
    }

#pragma unroll
    for (int p = 0; p < 4; p++) {
        float2 c0 = unpack2(acc[p][0]), c1 = unpack2(acc[p][1]),
               c2 = unpack2(acc[p][2]), c3 = unpack2(acc[p][3]);
        int row0 = rbase + rb + 2 * p;
        if (row0 < NN) {
            float s = g_dinv1[row0];
            *(float4*)&g_xw[(size_t)row0 * 128 + cb] =
                make_float4(c0.x * s, c1.x * s, c2.x * s, c3.x * s);
        }
        int row1 = row0 + 1;
        if (row1 < NN) {
            float s = g_dinv1[row1];
            *(float4*)&g_xw[(size_t)row1 * 128 + cb] =
                make_float4(c0.y * s, c1.y * s, c2.y * s, c3.y * s);
        }
    }
}

// ---------------- GEMM2: g_xw[:,0:64] = (h @ W2) * dinv2[row] ----------------
__global__ void k_gemm2(const float* __restrict__ W) {
    extern __shared__ float sm[];
    float* Ws = sm;              // 128*64
    float* Xs = sm + 128 * 64;   // 128 * 66
    const int tid = threadIdx.x;
    const int rbase = blockIdx.x * 64;

    const float4* W4 = (const float4*)W;
    float4* Ws4 = (float4*)Ws;
#pragma unroll
    for (int i = 0; i < 8; i++) Ws4[i * 256 + tid] = W4[i * 256 + tid];

#pragma unroll
    for (int it = 0; it < 32; it++) {
        int idx = it * 256 + tid;
        int r = idx >> 7, k = idx & 127;
        int row = rbase + r;
        Xs[k * 66 + r] = (row < NN) ? g_h[(size_t)row * 128 + k] : 0.f;
    }
    __syncthreads();

    const int tx = tid & 15, ty = tid >> 4;
    const int cb = tx * 4, rb = ty * 4;
    unsigned long long acc[2][4];
#pragma unroll
    for (int p = 0; p < 2; p++)
#pragma unroll
        for (int c = 0; c < 4; c++) acc[p][c] = 0ull;

#pragma unroll 4
    for (int k = 0; k < 128; k++) {
        float4 w4 = *(const float4*)(Ws + k * 64 + cb);
        unsigned long long wd0 = pack_dup(w4.x), wd1 = pack_dup(w4.y),
                           wd2 = pack_dup(w4.z), wd3 = pack_dup(w4.w);
        const float* xrow = Xs + k * 66 + rb;
#pragma unroll
        for (int p = 0; p < 2; p++) {
            unsigned long long a2 = pack2f(*(const float2*)(xrow + 2 * p));
            fma2(acc[p][0], a2, wd0);
            fma2(acc[p][1], a2, wd1);
            fma2(acc[p][2], a2, wd2);
            fma2(acc[p][3], a2, wd3);
        }
    }

#pragma unroll
    for (int p = 0; p < 2; p++) {
        float2 c0 = unpack2(acc[p][0]), c1 = unpack2(acc[p][1]),
               c2 = unpack2(acc[p][2]), c3 = unpack2(acc[p][3]);
        int row0 = rbase + rb + 2 * p;
        if (row0 < NN) {
            float s = g_dinv2[row0];
            *(float4*)&g_xw[(size_t)row0 * 64 + cb] =
                make_float4(c0.x * s, c1.x * s, c2.x * s, c3.x * s);
        }
        int row1 = row0 + 1;
        if (row1 < NN) {
            float s = g_dinv2[row1];
            *(float4*)&g_xw[(size_t)row1 * 64 + cb] =
                make_float4(c0.y * s, c1.y * s, c2.y * s, c3.y * s);
        }
    }
}

// ---------------- gather layer 1: warp per dst node, 128 ch; fused bias+PReLU ----------------
__global__ void k_gather1(const float* __restrict__ b, const float* __restrict__ al) {
    int gid = blockIdx.x * 256 + threadIdx.x;   // NN*32 threads exactly
    int node = gid >> 5;
    int lane = gid & 31;
    int beg = g_off[node], end = g_off[node + 1];

    // self loop: g_xw[node] already carries dinv1[node]
    float4 acc = *(const float4*)&g_xw[(size_t)node * 128 + lane * 4];

    int i = beg;
    for (; i + 1 < end; i += 2) {
        int2 e0 = g_e1[i];
        int2 e1 = g_e1[i + 1];
        float4 v0 = *(const float4*)&g_xw[(size_t)e0.x * 128 + lane * 4];
        float4 v1 = *(const float4*)&g_xw[(size_t)e1.x * 128 + lane * 4];
        float w0 = __int_as_float(e0.y), w1 = __int_as_float(e1.y);
        acc.x += w0 * v0.x + w1 * v1.x;
        acc.y += w0 * v0.y + w1 * v1.y;
        acc.z += w0 * v0.z + w1 * v1.z;
        acc.w += w0 * v0.w + w1 * v1.w;
    }
    if (i < end) {
        int2 e0 = g_e1[i];
        float4 v0 = *(const float4*)&g_xw[(size_t)e0.x * 128 + lane * 4];
        float w0 = __int_as_float(e0.y);
        acc.x += w0 * v0.x; acc.y += w0 * v0.y; acc.z += w0 * v0.z; acc.w += w0 * v0.w;
    }

    float s = g_dinv1[node];
    float4 bb = *(const float4*)&b[lane * 4];
    float4 aa = *(const float4*)&al[lane * 4];
    acc.x = acc.x * s + bb.x; acc.y = acc.y * s + bb.y;
    acc.z = acc.z * s + bb.z; acc.w = acc.w * s + bb.w;
    acc.x = (acc.x >= 0.f) ? acc.x : aa.x * acc.x;
    acc.y = (acc.y >= 0.f) ? acc.y : aa.y * acc.y;
    acc.z = (acc.z >= 0.f) ? acc.z : aa.z * acc.z;
    acc.w = (acc.w >= 0.f) ? acc.w : aa.w * acc.w;
    *(float4*)&g_h[(size_t)node * 128 + lane * 4] = acc;
}

// ---------------- gather layer 2: half-warp per dst node, 64 ch; fused bias+PReLU ----------------
__global__ void k_gather2(const float* __restrict__ b, const float* __restrict__ al) {
    int gid = blockIdx.x * 256 + threadIdx.x;   // NN*16 threads exactly
    int node = gid >> 4;
    int l16 = gid & 15;
    int beg = g_off[node], end = g_off[node + 1];

    float4 acc = *(const float4*)&g_xw[(size_t)node * 64 + l16 * 4];

    int i = beg;
    for (; i + 1 < end; i += 2) {
        int2 e0 = g_e2[i];
        int2 e1 = g_e2[i + 1];
        float4 v0 = *(const float4*)&g_xw[(size_t)e0.x * 64 + l16 * 4];
        float4 v1 = *(const float4*)&g_xw[(size_t)e1.x * 64 + l16 * 4];
        float w0 = __int_as_float(e0.y), w1 = __int_as_float(e1.y);
        acc.x += w0 * v0.x + w1 * v1.x;
        acc.y += w0 * v0.y + w1 * v1.y;
        acc.z += w0 * v0.z + w1 * v1.z;
        acc.w += w0 * v0.w + w1 * v1.w;
    }
    if (i < end) {
        int2 e0 = g_e2[i];
        float4 v0 = *(const float4*)&g_xw[(size_t)e0.x * 64 + l16 * 4];
        float w0 = __int_as_float(e0.y);
        acc.x += w0 * v0.x; acc.y += w0 * v0.y; acc.z += w0 * v0.z; acc.w += w0 * v0.w;
    }

    float s = g_dinv2[node];
    float4 bb = *(const float4*)&b[l16 * 4];
    float4 aa = *(const float4*)&al[l16 * 4];
    acc.x = acc.x * s + bb.x; acc.y = acc.y * s + bb.y;
    acc.z = acc.z * s + bb.z; acc.w = acc.w * s + bb.w;
    acc.x = (acc.x >= 0.f) ? acc.x : aa.x * acc.x;
    acc.y = (acc.y >= 0.f) ? acc.y : aa.y * acc.y;
    acc.z = (acc.z >= 0.f) ? acc.z : aa.z * acc.z;
    acc.w = (acc.w >= 0.f) ? acc.w : aa.w * acc.w;
    *(float4*)&g_h2[(size_t)node * 64 + l16 * 4] = acc;
}

// ---------------- half-combine ----------------
__global__ void k_final(float* __restrict__ out) {
    int gid = blockIdx.x * 256 + threadIdx.x;   // HALF*16 threads exactly
    int i = gid >> 4, q = gid & 15;
    float4 a = *(const float4*)&g_h2[(size_t)i * 64 + q * 4];
    float4 c = *(const float4*)&g_h2[(size_t)(i + HALF) * 64 + q * 4];
    *(float4*)&out[(size_t)i * 64 + q * 4] =
        make_float4(0.5f * (a.x + c.x), 0.5f * (a.y + c.y),
                    0.5f * (a.z + c.z), 0.5f * (a.w + c.w));
}

// ---------------- launch ----------------
extern "C" void kernel_launch(void* const* d_in, const int* in_sizes, int n_in,
                              void* d_out, int out_size) {
    (void)in_sizes; (void)n_in; (void)out_size;
    const float* x   = (const float*)d_in[0];
    const int*   ei  = (const int*)d_in[1];
    const float* ew  = (const float*)d_in[2];
    const int*   et  = (const int*)d_in[3];
    const float* W1  = (const float*)d_in[4];
    const float* b1  = (const float*)d_in[5];
    const float* a1  = (const float*)d_in[6];
    const float* W2  = (const float*)d_in[7];
    const float* b2  = (const float*)d_in[8];
    const float* a2  = (const float*)d_in[9];
    float* out = (float*)d_out;

    const int smem1 = (128 * 128 + 128 * 66) * sizeof(float);
    const int smem2 = (128 * 64  + 128 * 66) * sizeof(float);
    cudaFuncSetAttribute(k_gemm1, cudaFuncAttributeMaxDynamicSharedMemorySize, smem1);
    cudaFuncSetAttribute(k_gemm2, cudaFuncAttributeMaxDynamicSharedMemorySize, smem2);

    const int gemm_blocks = (NN + 63) / 64;

    // CSR build + degrees
    k_init<<<(NN + 255) / 256, 256>>>();
    k_hist<<<(EE + 255) / 256, 256>>>(ei, ew, et);
    k_dinv<<<(NN + 255) / 256, 256>>>();
    k_scan<<<1, 1024>>>();
    k_fill<<<(EE + 255) / 256, 256>>>(ei, ew, et);

    // layer 1
    k_gemm1<<<gemm_blocks, 256, smem1>>>(x, W1);
    k_gather1<<<NN * 32 / 256, 256>>>(b1, a1);

    // layer 2
    k_gemm2<<<gemm_blocks, 256, smem2>>>(W2);
    k_gather2<<<NN * 16 / 256, 256>>>(b2, a2);

    k_final<<<HALF * 16 / 256, 256>>>(out);
}

// round 4
// speedup vs baseline: 1.4869x; 1.4782x over previous
#include <cuda_runtime.h>
#include <cuda_bf16.h>

#define NN   100000
#define EE   1600000
#define HALF (NN/2)
#define SCAN_BLOCKS 98   // 98*1024 = 100352 >= NN

// ---------------- scratch (device globals; allocation-free) ----------------
__device__ float g_xw[(size_t)NN * 128];   // (x@W)*dinv[row]  (layer2 uses first NN*64)
__device__ float g_h[(size_t)NN * 128];    // layer-1 activations
__device__ float g_h2[(size_t)NN * 64];    // layer-2 activations (pre-combine)
__device__ float g_deg1[NN], g_deg2[NN], g_dinv1[NN], g_dinv2[NN];
__device__ int   g_hist[NN];
__device__ int   g_off[NN + 1];
__device__ int   g_cur[NN];
__device__ int   g_bsum[SCAN_BLOCKS];
__device__ int2  g_e1[EE];                 // (src, w1 bits) sorted by dst
__device__ int2  g_e2[EE];                 // (src, w2 bits) sorted by dst

// ---------------- packed f32x2 helpers (sm_103a FFMA2) ----------------
__device__ __forceinline__ unsigned long long pack_dup(float a) {
    unsigned long long r;
    asm("mov.b64 %0, {%1, %1};" : "=l"(r) : "r"(__float_as_uint(a)));
    return r;
}
__device__ __forceinline__ unsigned long long pack2f(float2 v) {
    unsigned long long r;
    asm("mov.b64 %0, {%1, %2};" : "=l"(r) : "r"(__float_as_uint(v.x)), "r"(__float_as_uint(v.y)));
    return r;
}
__device__ __forceinline__ float2 unpack2(unsigned long long v) {
    unsigned int lo, hi;
    asm("mov.b64 {%0, %1}, %2;" : "=r"(lo), "=r"(hi) : "l"(v));
    return make_float2(__uint_as_float(lo), __uint_as_float(hi));
}
__device__ __forceinline__ void fma2(unsigned long long& d, unsigned long long a, unsigned long long b) {
    asm("fma.rn.f32x2 %0, %1, %2, %0;" : "+l"(d) : "l"(a), "l"(b));
}

// ---------------- CSR build ----------------
__global__ void k_init() {
    int i = blockIdx.x * 256 + threadIdx.x;
    if (i < NN) { g_hist[i] = 0; g_deg1[i] = 1.0f; g_deg2[i] = 1.0f; }
}
__global__ void k_hist(const int* __restrict__ ei, const float* __restrict__ w,
                       const int* __restrict__ et) {
    int e = blockIdx.x * 256 + threadIdx.x;
    if (e < EE) {
        int dst = ei[EE + e];
        atomicAdd(&g_hist[dst], 1);
        atomicAdd(&g_deg1[dst], w[e]);
        atomicAdd(&g_deg2[dst], (float)et[e]);
    }
}
__global__ void k_dinv() {
    int i = blockIdx.x * 256 + threadIdx.x;
    if (i < NN) {
        float d1 = g_deg1[i], d2 = g_deg2[i];
        g_dinv1[i] = (d1 > 0.f) ? rsqrtf(d1) : 0.f;
        g_dinv2[i] = (d2 > 0.f) ? rsqrtf(d2) : 0.f;
    }
}

// ---- scan phase 1: per-block exclusive scan + block sums ----
__global__ void k_scan1() {
    __shared__ int wsum[32];
    const int tid = threadIdx.x;
    const int lane = tid & 31, wid = tid >> 5;
    int i = blockIdx.x * 1024 + tid;
    int v = (i < NN) ? g_hist[i] : 0;
    int x = v;
#pragma unroll
    for (int o = 1; o < 32; o <<= 1) {
        int y = __shfl_up_sync(0xffffffffu, x, o);
        if (lane >= o) x += y;
    }
    if (lane == 31) wsum[wid] = x;
    __syncthreads();
    if (wid == 0) {
        int s = wsum[lane];
#pragma unroll
        for (int o = 1; o < 32; o <<= 1) {
            int y = __shfl_up_sync(0xffffffffu, s, o);
            if (lane >= o) s += y;
        }
        wsum[lane] = s;
    }
    __syncthreads();
    int excl = (x - v) + ((wid > 0) ? wsum[wid - 1] : 0);
    if (i < NN) g_off[i] = excl;
    if (tid == 0) g_bsum[blockIdx.x] = wsum[31];
}

// ---- scan phase 2: exclusive scan of 98 block sums (1 block, 128 thr) ----
__global__ void k_scan2() {
    __shared__ int ws[4];
    const int tid = threadIdx.x;
    const int lane = tid & 31, wid = tid >> 5;
    int v = (tid < SCAN_BLOCKS) ? g_bsum[tid] : 0;
    int x = v;
#pragma unroll
    for (int o = 1; o < 32; o <<= 1) {
        int y = __shfl_up_sync(0xffffffffu, x, o);
        if (lane >= o) x += y;
    }
    if (lane == 31) ws[wid] = x;
    __syncthreads();
    int add = 0;
#pragma unroll
    for (int w = 0; w < 4; w++) add += (w < wid) ? ws[w] : 0;
    if (tid < SCAN_BLOCKS) g_bsum[tid] = (x - v) + add;   // exclusive
}

// ---- scan phase 3: add block offsets, init g_cur, set sentinel ----
__global__ void k_scan3() {
    int i = blockIdx.x * 1024 + threadIdx.x;
    if (i < NN) {
        int o = g_off[i] + g_bsum[i >> 10];
        g_off[i] = o;
        g_cur[i] = o;
    }
    if (i == 0) g_off[NN] = EE;   // total edge count is a compile-time constant
}

__global__ void k_fill(const int* __restrict__ ei, const float* __restrict__ w,
                       const int* __restrict__ et) {
    int e = blockIdx.x * 256 + threadIdx.x;
    if (e < EE) {
        int src = ei[e];
        int dst = ei[EE + e];
        int pos = atomicAdd(&g_cur[dst], 1);
        g_e1[pos] = make_int2(src, __float_as_int(w[e]));
        g_e2[pos] = make_int2(src, __float_as_int((float)et[e]));
    }
}

// ---------------- GEMM1: g_xw = (x @ W1) * dinv1[row] ----------------
__global__ void k_gemm1(const float* __restrict__ x, const float* __restrict__ W) {
    extern __shared__ float sm[];
    float* Ws = sm;              // 128*128
    float* Xs = sm + 128 * 128;  // 128 * 66
    const int tid = threadIdx.x;
    const int rbase = blockIdx.x * 64;

    const float4* W4 = (const float4*)W;
    float4* Ws4 = (float4*)Ws;
#pragma unroll
    for (int i = 0; i < 16; i++) Ws4[i * 256 + tid] = W4[i * 256 + tid];

#pragma unroll
    for (int it = 0; it < 32; it++) {
        int idx = it * 256 + tid;
        int r = idx >> 7, k = idx & 127;
        int row = rbase + r;
        Xs[k * 66 + r] = (row < NN) ? x[(size_t)row * 128 + k] : 0.f;
    }
    __syncthreads();

    const int tx = tid & 31, ty = tid >> 5;
    const int cb = tx * 4, rb = ty * 8;
    unsigned long long acc[4][4];
#pragma unroll
    for (int p = 0; p < 4; p++)
#pragma unroll
        for (int c = 0; c < 4; c++) acc[p][c] = 0ull;

#pragma unroll 4
    for (int k = 0; k < 128; k++) {
        float4 w4 = *(const float4*)(Ws + k * 128 + cb);
        unsigned long long wd0 = pack_dup(w4.x), wd1 = pack_dup(w4.y),
                           wd2 = pack_dup(w4.z), wd3 = pack_dup(w4.w);
        const float* xrow = Xs + k * 66 + rb;
#pragma unroll
        for (int p = 0; p < 4; p++) {
            unsigned long long a2 = pack2f(*(const float2*)(xrow + 2 * p));
            fma2(acc[p][0], a2, wd0);
            fma2(acc[p][1], a2, wd1);
            fma2(acc[p][2], a2, wd2);
            fma2(acc[p][3], a2, wd3);
        }
    }

#pragma unroll
    for (int p = 0; p < 4; p++) {
        float2 c0 = unpack2(acc[p][0]), c1 = unpack2(acc[p][1]),
               c2 = unpack2(acc[p][2]), c3 = unpack2(acc[p][3]);
        int row0 = rbase + rb + 2 * p;
        if (row0 < NN) {
            float s = g_dinv1[row0];
            *(float4*)&g_xw[(size_t)row0 * 128 + cb] =
                make_float4(c0.x * s, c1.x * s, c2.x * s, c3.x * s);
        }
        int row1 = row0 + 1;
        if (row1 < NN) {
            float s = g_dinv1[row1];
            *(float4*)&g_xw[(size_t)row1 * 128 + cb] =
                make_float4(c0.y * s, c1.y * s, c2.y * s, c3.y * s);
        }
    }
}

// ---------------- GEMM2: g_xw[:,0:64] = (h @ W2) * dinv2[row] ----------------
__global__ void k_gemm2(const float* __restrict__ W) {
    extern __shared__ float sm[];
    float* Ws = sm;              // 128*64
    float* Xs = sm + 128 * 64;   // 128 * 66
    const int tid = threadIdx.x;
    const int rbase = blockIdx.x * 64;

    const float4* W4 = (const float4*)W;
    float4* Ws4 = (float4*)Ws;
#pragma unroll
    for (int i = 0; i < 8; i++) Ws4[i * 256 + tid] = W4[i * 256 + tid];

#pragma unroll
    for (int it = 0; it < 32; it++) {
        int idx = it * 256 + tid;
        int r = idx >> 7, k = idx & 127;
        int row = rbase + r;
        Xs[k * 66 + r] = (row < NN) ? g_h[(size_t)row * 128 + k] : 0.f;
    }
    __syncthreads();

    const int tx = tid & 15, ty = tid >> 4;
    const int cb = tx * 4, rb = ty * 4;
    unsigned long long acc[2][4];
#pragma unroll
    for (int p = 0; p < 2; p++)
#pragma unroll
        for (int c = 0; c < 4; c++) acc[p][c] = 0ull;

#pragma unroll 4
    for (int k = 0; k < 128; k++) {
        float4 w4 = *(const float4*)(Ws + k * 64 + cb);
        unsigned long long wd0 = pack_dup(w4.x), wd1 = pack_dup(w4.y),
                           wd2 = pack_dup(w4.z), wd3 = pack_dup(w4.w);
        const float* xrow = Xs + k * 66 + rb;
#pragma unroll
        for (int p = 0; p < 2; p++) {
            unsigned long long a2 = pack2f(*(const float2*)(xrow + 2 * p));
            fma2(acc[p][0], a2, wd0);
            fma2(acc[p][1], a2, wd1);
            fma2(acc[p][2], a2, wd2);
            fma2(acc[p][3], a2, wd3);
        }
    }

#pragma unroll
    for (int p = 0; p < 2; p++) {
        float2 c0 = unpack2(acc[p][0]), c1 = unpack2(acc[p][1]),
               c2 = unpack2(acc[p][2]), c3 = unpack2(acc[p][3]);
        int row0 = rbase + rb + 2 * p;
        if (row0 < NN) {
            float s = g_dinv2[row0];
            *(float4*)&g_xw[(size_t)row0 * 64 + cb] =
                make_float4(c0.x * s, c1.x * s, c2.x * s, c3.x * s);
        }
        int row1 = row0 + 1;
        if (row1 < NN) {
            float s = g_dinv2[row1];
            *(float4*)&g_xw[(size_t)row1 * 64 + cb] =
                make_float4(c0.y * s, c1.y * s, c2.y * s, c3.y * s);
        }
    }
}

// ---------------- gather layer 1: warp per dst node, 128 ch; fused bias+PReLU ----------------
__global__ void k_gather1(const float* __restrict__ b, const float* __restrict__ al) {
    int gid = blockIdx.x * 256 + threadIdx.x;   // NN*32 threads exactly
    int node = gid >> 5;
    int lane = gid & 31;
    int beg = g_off[node], end = g_off[node + 1];

    // self loop: g_xw[node] already carries dinv1[node]
    float4 acc = *(const float4*)&g_xw[(size_t)node * 128 + lane * 4];

    int i = beg;
    for (; i + 1 < end; i += 2) {
        int2 e0 = g_e1[i];
        int2 e1 = g_e1[i + 1];
        float4 v0 = *(const float4*)&g_xw[(size_t)e0.x * 128 + lane * 4];
        float4 v1 = *(const float4*)&g_xw[(size_t)e1.x * 128 + lane * 4];
        float w0 = __int_as_float(e0.y), w1 = __int_as_float(e1.y);
        acc.x += w0 * v0.x + w1 * v1.x;
        acc.y += w0 * v0.y + w1 * v1.y;
        acc.z += w0 * v0.z + w1 * v1.z;
        acc.w += w0 * v0.w + w1 * v1.w;
    }
    if (i < end) {
        int2 e0 = g_e1[i];
        float4 v0 = *(const float4*)&g_xw[(size_t)e0.x * 128 + lane * 4];
        float w0 = __int_as_float(e0.y);
        acc.x += w0 * v0.x; acc.y += w0 * v0.y; acc.z += w0 * v0.z; acc.w += w0 * v0.w;
    }

    float s = g_dinv1[node];
    float4 bb = *(const float4*)&b[lane * 4];
    float4 aa = *(const float4*)&al[lane * 4];
    acc.x = acc.x * s + bb.x; acc.y = acc.y * s + bb.y;
    acc.z = acc.z * s + bb.z; acc.w = acc.w * s + bb.w;
    acc.x = (acc.x >= 0.f) ? acc.x : aa.x * acc.x;
    acc.y = (acc.y >= 0.f) ? acc.y : aa.y * acc.y;
    acc.z = (acc.z >= 0.f) ? acc.z : aa.z * acc.z;
    acc.w = (acc.w >= 0.f) ? acc.w : aa.w * acc.w;
    *(float4*)&g_h[(size_t)node * 128 + lane * 4] = acc;
}

// ---------------- gather layer 2: half-warp per dst node, 64 ch; fused bias+PReLU ----------------
__global__ void k_gather2(const float* __restrict__ b, const float* __restrict__ al) {
    int gid = blockIdx.x * 256 + threadIdx.x;   // NN*16 threads exactly
    int node = gid >> 4;
    int l16 = gid & 15;
    int beg = g_off[node], end = g_off[node + 1];

    float4 acc = *(const float4*)&g_xw[(size_t)node * 64 + l16 * 4];

    int i = beg;
    for (; i + 1 < end; i += 2) {
        int2 e0 = g_e2[i];
        int2 e1 = g_e2[i + 1];
        float4 v0 = *(const float4*)&g_xw[(size_t)e0.x * 64 + l16 * 4];
        float4 v1 = *(const float4*)&g_xw[(size_t)e1.x * 64 + l16 * 4];
        float w0 = __int_as_float(e0.y), w1 = __int_as_float(e1.y);
        acc.x += w0 * v0.x + w1 * v1.x;
        acc.y += w0 * v0.y + w1 * v1.y;
        acc.z += w0 * v0.z + w1 * v1.z;
        acc.w += w0 * v0.w + w1 * v1.w;
    }
    if (i < end) {
        int2 e0 = g_e2[i];
        float4 v0 = *(const float4*)&g_xw[(size_t)e0.x * 64 + l16 * 4];
        float w0 = __int_as_float(e0.y);
        acc.x += w0 * v0.x; acc.y += w0 * v0.y; acc.z += w0 * v0.z; acc.w += w0 * v0.w;
    }

    float s = g_dinv2[node];
    float4 bb = *(const float4*)&b[l16 * 4];
    float4 aa = *(const float4*)&al[l16 * 4];
    acc.x = acc.x * s + bb.x; acc.y = acc.y * s + bb.y;
    acc.z = acc.z * s + bb.z; acc.w = acc.w * s + bb.w;
    acc.x = (acc.x >= 0.f) ? acc.x : aa.x * acc.x;
    acc.y = (acc.y >= 0.f) ? acc.y : aa.y * acc.y;
    acc.z = (acc.z >= 0.f) ? acc.z : aa.z * acc.z;
    acc.w = (acc.w >= 0.f) ? acc.w : aa.w * acc.w;
    *(float4*)&g_h2[(size_t)node * 64 + l16 * 4] = acc;
}

// ---------------- half-combine ----------------
__global__ void k_final(float* __restrict__ out) {
    int gid = blockIdx.x * 256 + threadIdx.x;   // HALF*16 threads exactly
    int i = gid >> 4, q = gid & 15;
    float4 a = *(const float4*)&g_h2[(size_t)i * 64 + q * 4];
    float4 c = *(const float4*)&g_h2[(size_t)(i + HALF) * 64 + q * 4];
    *(float4*)&out[(size_t)i * 64 + q * 4] =
        make_float4(0.5f * (a.x + c.x), 0.5f * (a.y + c.y),
                    0.5f * (a.z + c.z), 0.5f * (a.w + c.w));
}

// ---------------- launch ----------------
extern "C" void kernel_launch(void* const* d_in, const int* in_sizes, int n_in,
                              void* d_out, int out_size) {
    (void)in_sizes; (void)n_in; (void)out_size;
    const float* x   = (const float*)d_in[0];
    const int*   ei  = (const int*)d_in[1];
    const float* ew  = (const float*)d_in[2];
    const int*   et  = (const int*)d_in[3];
    const float* W1  = (const float*)d_in[4];
    const float* b1  = (const float*)d_in[5];
    const float* a1  = (const float*)d_in[6];
    const float* W2  = (const float*)d_in[7];
    const float* b2  = (const float*)d_in[8];
    const float* a2  = (const float*)d_in[9];
    float* out = (float*)d_out;

    const int smem1 = (128 * 128 + 128 * 66) * sizeof(float);
    const int smem2 = (128 * 64  + 128 * 66) * sizeof(float);
    cudaFuncSetAttribute(k_gemm1, cudaFuncAttributeMaxDynamicSharedMemorySize, smem1);
    cudaFuncSetAttribute(k_gemm2, cudaFuncAttributeMaxDynamicSharedMemorySize, smem2);

    const int gemm_blocks = (NN + 63) / 64;

    // CSR build + degrees
    k_init<<<(NN + 255) / 256, 256>>>();
    k_hist<<<(EE + 255) / 256, 256>>>(ei, ew, et);
    k_dinv<<<(NN + 255) / 256, 256>>>();
    k_scan1<<<SCAN_BLOCKS, 1024>>>();
    k_scan2<<<1, 128>>>();
    k_scan3<<<SCAN_BLOCKS, 1024>>>();
    k_fill<<<(EE + 255) / 256, 256>>>(ei, ew, et);

    // layer 1
    k_gemm1<<<gemm_blocks, 256, smem1>>>(x, W1);
    k_gather1<<<NN * 32 / 256, 256>>>(b1, a1);

    // layer 2
    k_gemm2<<<gemm_blocks, 256, smem2>>>(W2);
    k_gather2<<<NN * 16 / 256, 256>>>(b2, a2);

    k_final<<<HALF * 16 / 256, 256>>>(out);
}

// round 5
// speedup vs baseline: 1.5577x; 1.0476x over previous
#include <cuda_runtime.h>
#include <cuda_bf16.h>

#define NN   100000
#define EE   1600000
#define HALF (NN/2)
#define SCAN_BLOCKS 98   // 98*1024 = 100352 >= NN

// ---------------- scratch (device globals; allocation-free) ----------------
__device__ float g_xw[(size_t)NN * 128];   // x@W (unscaled)  (layer2 uses first NN*64)
__device__ float g_h[(size_t)NN * 128];    // layer-1 activations
__device__ float g_h2[(size_t)NN * 64];    // layer-2 activations (pre-combine)
__device__ float g_deg1[NN], g_deg2[NN], g_dinv1[NN], g_dinv2[NN];
__device__ int   g_hist[NN],  g_hist2[NN];
__device__ int   g_off[NN + 1], g_off2[NN + 1];
__device__ int   g_cur[NN],   g_cur2[NN];
__device__ int   g_bsum[SCAN_BLOCKS], g_bsum2[SCAN_BLOCKS];
__device__ int2  g_e1[EE];                 // (src, ew*dinv1[src]) grouped by dst
__device__ int2  g_e2[EE];                 // (src, et*dinv2[src]) grouped by dst, et>0 only

// ---------------- packed f32x2 helpers (sm_103a FFMA2) ----------------
__device__ __forceinline__ unsigned long long pack_dup(float a) {
    unsigned long long r;
    asm("mov.b64 %0, {%1, %1};" : "=l"(r) : "r"(__float_as_uint(a)));
    return r;
}
__device__ __forceinline__ unsigned long long pack2f(float2 v) {
    unsigned long long r;
    asm("mov.b64 %0, {%1, %2};" : "=l"(r) : "r"(__float_as_uint(v.x)), "r"(__float_as_uint(v.y)));
    return r;
}
__device__ __forceinline__ float2 unpack2(unsigned long long v) {
    unsigned int lo, hi;
    asm("mov.b64 {%0, %1}, %2;" : "=r"(lo), "=r"(hi) : "l"(v));
    return make_float2(__uint_as_float(lo), __uint_as_float(hi));
}
__device__ __forceinline__ void fma2(unsigned long long& d, unsigned long long a, unsigned long long b) {
    asm("fma.rn.f32x2 %0, %1, %2, %0;" : "+l"(d) : "l"(a), "l"(b));
}

// ---------------- CSR build ----------------
__global__ void k_init() {
    int i = blockIdx.x * 256 + threadIdx.x;
    if (i < NN) {
        g_hist[i] = 0; g_hist2[i] = 0;
        g_deg1[i] = 1.0f; g_deg2[i] = 1.0f;   // self-loop weight 1
    }
}
__global__ void k_hist(const int* __restrict__ ei, const float* __restrict__ w,
                       const int* __restrict__ et) {
    int e = blockIdx.x * 256 + threadIdx.x;
    if (e < EE) {
        int dst = ei[EE + e];
        int t = et[e];
        atomicAdd(&g_hist[dst], 1);
        if (t > 0) {
            atomicAdd(&g_hist2[dst], 1);
            atomicAdd(&g_deg2[dst], (float)t);
        }
        atomicAdd(&g_deg1[dst], w[e]);
    }
}
__global__ void k_dinv() {
    int i = blockIdx.x * 256 + threadIdx.x;
    if (i < NN) {
        float d1 = g_deg1[i], d2 = g_deg2[i];
        g_dinv1[i] = (d1 > 0.f) ? rsqrtf(d1) : 0.f;
        g_dinv2[i] = (d2 > 0.f) ? rsqrtf(d2) : 0.f;
    }
}

__device__ __forceinline__ int warp_excl_scan(int v, int lane) {
    int x = v;
#pragma unroll
    for (int o = 1; o < 32; o <<= 1) {
        int y = __shfl_up_sync(0xffffffffu, x, o);
        if (lane >= o) x += y;
    }
    return x;   // inclusive; caller subtracts v for exclusive
}

// ---- scan phase 1 (both hist arrays): per-block exclusive scan + block sums ----
__global__ void k_scanA() {
    __shared__ int wsum[32], wsum2[32];
    const int tid = threadIdx.x;
    const int lane = tid & 31, wid = tid >> 5;
    int i = blockIdx.x * 1024 + tid;
    int v1 = (i < NN) ? g_hist[i] : 0;
    int v2 = (i < NN) ? g_hist2[i] : 0;
    int x1 = warp_excl_scan(v1, lane);
    int x2 = warp_excl_scan(v2, lane);
    if (lane == 31) { wsum[wid] = x1; wsum2[wid] = x2; }
    __syncthreads();
    if (wid == 0) {
        int s1 = warp_excl_scan(wsum[lane], lane);
        int s2 = warp_excl_scan(wsum2[lane], lane);
        wsum[lane] = s1; wsum2[lane] = s2;
    }
    __syncthreads();
    int e1 = (x1 - v1) + ((wid > 0) ? wsum[wid - 1] : 0);
    int e2 = (x2 - v2) + ((wid > 0) ? wsum2[wid - 1] : 0);
    if (i < NN) { g_off[i] = e1; g_off2[i] = e2; }
    if (tid == 0) { g_bsum[blockIdx.x] = wsum[31]; g_bsum2[blockIdx.x] = wsum2[31]; }
}

// ---- scan phase 2: exclusive scan of block sums (both), write totals ----
__global__ void k_scanB() {
    __shared__ int ws[4], ws2[4];
    const int tid = threadIdx.x;                 // 128 threads
    const int lane = tid & 31, wid = tid >> 5;
    int v1 = (tid < SCAN_BLOCKS) ? g_bsum[tid] : 0;
    int v2 = (tid < SCAN_BLOCKS) ? g_bsum2[tid] : 0;
    int x1 = warp_excl_scan(v1, lane);
    int x2 = warp_excl_scan(v2, lane);
    if (lane == 31) { ws[wid] = x1; ws2[wid] = x2; }
    __syncthreads();
    int add1 = 0, add2 = 0;
#pragma unroll
    for (int w = 0; w < 4; w++) {
        add1 += (w < wid) ? ws[w] : 0;
        add2 += (w < wid) ? ws2[w] : 0;
    }
    if (tid < SCAN_BLOCKS) {
        g_bsum[tid]  = (x1 - v1) + add1;
        g_bsum2[tid] = (x2 - v2) + add2;
        if (tid == SCAN_BLOCKS - 1) {
            g_off[NN]  = (x1 - v1) + add1 + v1;   // = EE
            g_off2[NN] = (x2 - v2) + add2 + v2;   // = #nonzero-type edges
        }
    }
}

// ---- scan phase 3: add block offsets, init cursors ----
__global__ void k_scanC() {
    int i = blockIdx.x * 1024 + threadIdx.x;
    if (i < NN) {
        int o1 = g_off[i]  + g_bsum[i >> 10];
        int o2 = g_off2[i] + g_bsum2[i >> 10];
        g_off[i] = o1;  g_cur[i] = o1;
        g_off2[i] = o2; g_cur2[i] = o2;
    }
}

__global__ void k_fill(const int* __restrict__ ei, const float* __restrict__ w,
                       const int* __restrict__ et) {
    int e = blockIdx.x * 256 + threadIdx.x;
    if (e < EE) {
        int src = ei[e];
        int dst = ei[EE + e];
        int pos = atomicAdd(&g_cur[dst], 1);
        g_e1[pos] = make_int2(src, __float_as_int(w[e] * g_dinv1[src]));
        int t = et[e];
        if (t > 0) {
            int pos2 = atomicAdd(&g_cur2[dst], 1);
            g_e2[pos2] = make_int2(src, __float_as_int((float)t * g_dinv2[src]));
        }
    }
}

// ---------------- GEMM1: g_xw = x @ W1 (unscaled) ----------------
__global__ void k_gemm1(const float* __restrict__ x, const float* __restrict__ W) {
    extern __shared__ float sm[];
    float* Ws = sm;              // 128*128
    float* Xs = sm + 128 * 128;  // 128 * 66
    const int tid = threadIdx.x;
    const int rbase = blockIdx.x * 64;

    const float4* W4 = (const float4*)W;
    float4* Ws4 = (float4*)Ws;
#pragma unroll
    for (int i = 0; i < 16; i++) Ws4[i * 256 + tid] = W4[i * 256 + tid];

#pragma unroll
    for (int it = 0; it < 32; it++) {
        int idx = it * 256 + tid;
        int r = idx >> 7, k = idx & 127;
        int row = rbase + r;
        Xs[k * 66 + r] = (row < NN) ? x[(size_t)row * 128 + k] : 0.f;
    }
    __syncthreads();

    const int tx = tid & 31, ty = tid >> 5;
    const int cb = tx * 4, rb = ty * 8;
    unsigned long long acc[4][4];
#pragma unroll
    for (int p = 0; p < 4; p++)
#pragma unroll
        for (int c = 0; c < 4; c++) acc[p][c] = 0ull;

#pragma unroll 4
    for (int k = 0; k < 128; k++) {
        float4 w4 = *(const float4*)(Ws + k * 128 + cb);
        unsigned long long wd0 = pack_dup(w4.x), wd1 = pack_dup(w4.y),
                           wd2 = pack_dup(w4.z), wd3 = pack_dup(w4.w);
        const float* xrow = Xs + k * 66 + rb;
#pragma unroll
        for (int p = 0; p < 4; p++) {
            unsigned long long a2 = pack2f(*(const float2*)(xrow + 2 * p));
            fma2(acc[p][0], a2, wd0);
            fma2(acc[p][1], a2, wd1);
            fma2(acc[p][2], a2, wd2);
            fma2(acc[p][3], a2, wd3);
        }
    }

#pragma unroll
    for (int p = 0; p < 4; p++) {
        float2 c0 = unpack2(acc[p][0]), c1 = unpack2(acc[p][1]),
               c2 = unpack2(acc[p][2]), c3 = unpack2(acc[p][3]);
        int row0 = rbase + rb + 2 * p;
        if (row0 < NN)
            *(float4*)&g_xw[(size_t)row0 * 128 + cb] = make_float4(c0.x, c1.x, c2.x, c3.x);
        int row1 = row0 + 1;
        if (row1 < NN)
            *(float4*)&g_xw[(size_t)row1 * 128 + cb] = make_float4(c0.y, c1.y, c2.y, c3.y);
    }
}

// ---------------- GEMM2: g_xw[:,0:64] = h @ W2 (unscaled) ----------------
__global__ void k_gemm2(const float* __restrict__ W) {
    extern __shared__ float sm[];
    float* Ws = sm;              // 128*64
    float* Xs = sm + 128 * 64;   // 128 * 66
    const int tid = threadIdx.x;
    const int rbase = blockIdx.x * 64;

    const float4* W4 = (const float4*)W;
    float4* Ws4 = (float4*)Ws;
#pragma unroll
    for (int i = 0; i < 8; i++) Ws4[i * 256 + tid] = W4[i * 256 + tid];

#pragma unroll
    for (int it = 0; it < 32; it++) {
        int idx = it * 256 + tid;
        int r = idx >> 7, k = idx & 127;
        int row = rbase + r;
        Xs[k * 66 + r] = (row < NN) ? g_h[(size_t)row * 128 + k] : 0.f;
    }
    __syncthreads();

    const int tx = tid & 15, ty = tid >> 4;
    const int cb = tx * 4, rb = ty * 4;
    unsigned long long acc[2][4];
#pragma unroll
    for (int p = 0; p < 2; p++)
#pragma unroll
        for (int c = 0; c < 4; c++) acc[p][c] = 0ull;

#pragma unroll 4
    for (int k = 0; k < 128; k++) {
        float4 w4 = *(const float4*)(Ws + k * 64 + cb);
        unsigned long long wd0 = pack_dup(w4.x), wd1 = pack_dup(w4.y),
                           wd2 = pack_dup(w4.z), wd3 = pack_dup(w4.w);
        const float* xrow = Xs + k * 66 + rb;
#pragma unroll
        for (int p = 0; p < 2; p++) {
            unsigned long long a2 = pack2f(*(const float2*)(xrow + 2 * p));
            fma2(acc[p][0], a2, wd0);
            fma2(acc[p][1], a2, wd1);
            fma2(acc[p][2], a2, wd2);
            fma2(acc[p][3], a2, wd3);
        }
    }

#pragma unroll
    for (int p = 0; p < 2; p++) {
        float2 c0 = unpack2(acc[p][0]), c1 = unpack2(acc[p][1]),
               c2 = unpack2(acc[p][2]), c3 = unpack2(acc[p][3]);
        int row0 = rbase + rb + 2 * p;
        if (row0 < NN)
            *(float4*)&g_xw[(size_t)row0 * 64 + cb] = make_float4(c0.x, c1.x, c2.x, c3.x);
        int row1 = row0 + 1;
        if (row1 < NN)
            *(float4*)&g_xw[(size_t)row1 * 64 + cb] = make_float4(c0.y, c1.y, c2.y, c3.y);
    }
}

// ---------------- gather layer 1: warp per dst node, 128 ch; fused bias+PReLU ----------------
__global__ void k_gather1(const float* __restrict__ b, const float* __restrict__ al) {
    int gid = blockIdx.x * 256 + threadIdx.x;   // NN*32 threads exactly
    int node = gid >> 5;
    int lane = gid & 31;
    int beg = g_off[node], end = g_off[node + 1];
    float s = g_dinv1[node];

    // self loop: contributes xw[node]*dinv^2; one factor here, one in epilogue
    float4 acc = *(const float4*)&g_xw[(size_t)node * 128 + lane * 4];
    acc.x *= s; acc.y *= s; acc.z *= s; acc.w *= s;

    int i = beg;
    for (; i + 1 < end; i += 2) {
        int2 e0 = g_e1[i];
        int2 e1 = g_e1[i + 1];
        float4 v0 = *(const float4*)&g_xw[(size_t)e0.x * 128 + lane * 4];
        float4 v1 = *(const float4*)&g_xw[(size_t)e1.x * 128 + lane * 4];
        float w0 = __int_as_float(e0.y), w1 = __int_as_float(e1.y);
        acc.x += w0 * v0.x + w1 * v1.x;
        acc.y += w0 * v0.y + w1 * v1.y;
        acc.z += w0 * v0.z + w1 * v1.z;
        acc.w += w0 * v0.w + w1 * v1.w;
    }
    if (i < end) {
        int2 e0 = g_e1[i];
        float4 v0 = *(const float4*)&g_xw[(size_t)e0.x * 128 + lane * 4];
        float w0 = __int_as_float(e0.y);
        acc.x += w0 * v0.x; acc.y += w0 * v0.y; acc.z += w0 * v0.z; acc.w += w0 * v0.w;
    }

    float4 bb = *(const float4*)&b[lane * 4];
    float4 aa = *(const float4*)&al[lane * 4];
    acc.x = acc.x * s + bb.x; acc.y = acc.y * s + bb.y;
    acc.z = acc.z * s + bb.z; acc.w = acc.w * s + bb.w;
    acc.x = (acc.x >= 0.f) ? acc.x : aa.x * acc.x;
    acc.y = (acc.y >= 0.f) ? acc.y : aa.y * acc.y;
    acc.z = (acc.z >= 0.f) ? acc.z : aa.z * acc.z;
    acc.w = (acc.w >= 0.f) ? acc.w : aa.w * acc.w;
    *(float4*)&g_h[(size_t)node * 128 + lane * 4] = acc;
}

// ---------------- gather layer 2: half-warp per dst node, 64 ch; fused bias+PReLU ----------------
__global__ void k_gather2(const float* __restrict__ b, const float* __restrict__ al) {
    int gid = blockIdx.x * 256 + threadIdx.x;   // NN*16 threads exactly
    int node = gid >> 4;
    int l16 = gid & 15;
    int beg = g_off2[node], end = g_off2[node + 1];
    float s = g_dinv2[node];

    float4 acc = *(const float4*)&g_xw[(size_t)node * 64 + l16 * 4];
    acc.x *= s; acc.y *= s; acc.z *= s; acc.w *= s;

    int i = beg;
    for (; i + 1 < end; i += 2) {
        int2 e0 = g_e2[i];
        int2 e1 = g_e2[i + 1];
        float4 v0 = *(const float4*)&g_xw[(size_t)e0.x * 64 + l16 * 4];
        float4 v1 = *(const float4*)&g_xw[(size_t)e1.x * 64 + l16 * 4];
        float w0 = __int_as_float(e0.y), w1 = __int_as_float(e1.y);
        acc.x += w0 * v0.x + w1 * v1.x;
        acc.y += w0 * v0.y + w1 * v1.y;
        acc.z += w0 * v0.z + w1 * v1.z;
        acc.w += w0 * v0.w + w1 * v1.w;
    }
    if (i < end) {
        int2 e0 = g_e2[i];
        float4 v0 = *(const float4*)&g_xw[(size_t)e0.x * 64 + l16 * 4];
        float w0 = __int_as_float(e0.y);
        acc.x += w0 * v0.x; acc.y += w0 * v0.y; acc.z += w0 * v0.z; acc.w += w0 * v0.w;
    }

    float4 bb = *(const float4*)&b[l16 * 4];
    float4 aa = *(const float4*)&al[l16 * 4];
    acc.x = acc.x * s + bb.x; acc.y = acc.y * s + bb.y;
    acc.z = acc.z * s + bb.z; acc.w = acc.w * s + bb.w;
    acc.x = (acc.x >= 0.f) ? acc.x : aa.x * acc.x;
    acc.y = (acc.y >= 0.f) ? acc.y : aa.y * acc.y;
    acc.z = (acc.z >= 0.f) ? acc.z : aa.z * acc.z;
    acc.w = (acc.w >= 0.f) ? acc.w : aa.w * acc.w;
    *(float4*)&g_h2[(size_t)node * 64 + l16 * 4] = acc;
}

// ---------------- half-combine ----------------
__global__ void k_final(float* __restrict__ out) {
    int gid = blockIdx.x * 256 + threadIdx.x;   // HALF*16 threads exactly
    int i = gid >> 4, q = gid & 15;
    float4 a = *(const float4*)&g_h2[(size_t)i * 64 + q * 4];
    float4 c = *(const float4*)&g_h2[(size_t)(i + HALF) * 64 + q * 4];
    *(float4*)&out[(size_t)i * 64 + q * 4] =
        make_float4(0.5f * (a.x + c.x), 0.5f * (a.y + c.y),
                    0.5f * (a.z + c.z), 0.5f * (a.w + c.w));
}

// ---------------- launch ----------------
extern "C" void kernel_launch(void* const* d_in, const int* in_sizes, int n_in,
                              void* d_out, int out_size) {
    (void)in_sizes; (void)n_in; (void)out_size;
    const float* x   = (const float*)d_in[0];
    const int*   ei  = (const int*)d_in[1];
    const float* ew  = (const float*)d_in[2];
    const int*   et  = (const int*)d_in[3];
    const float* W1  = (const float*)d_in[4];
    const float* b1  = (const float*)d_in[5];
    const float* a1  = (const float*)d_in[6];
    const float* W2  = (const float*)d_in[7];
    const float* b2  = (const float*)d_in[8];
    const float* a2  = (const float*)d_in[9];
    float* out = (float*)d_out;

    const int smem1 = (128 * 128 + 128 * 66) * sizeof(float);
    const int smem2 = (128 * 64  + 128 * 66) * sizeof(float);
    cudaFuncSetAttribute(k_gemm1, cudaFuncAttributeMaxDynamicSharedMemorySize, smem1);
    cudaFuncSetAttribute(k_gemm2, cudaFuncAttributeMaxDynamicSharedMemorySize, smem2);

    const int gemm_blocks = (NN + 63) / 64;

    // one-time side-stream + events (host resources, created once; same device
    // work is issued on every call regardless)
    static cudaStream_t s2 = nullptr;
    static cudaEvent_t evF = nullptr, evJ = nullptr;
    static bool tried = false;
    if (!tried) {
        tried = true;
        if (cudaStreamCreateWithFlags(&s2, cudaStreamNonBlocking) != cudaSuccess) s2 = nullptr;
        if (s2) {
            if (cudaEventCreateWithFlags(&evF, cudaEventDisableTiming) != cudaSuccess) { s2 = nullptr; }
            else if (cudaEventCreateWithFlags(&evJ, cudaEventDisableTiming) != cudaSuccess) { s2 = nullptr; }
        }
    }

    if (s2) {
        // fork: CSR build chain on s2, concurrent with gemm1 on main stream
        cudaEventRecord(evF, 0);
        cudaStreamWaitEvent(s2, evF, 0);
        k_init <<<(NN + 255) / 256, 256, 0, s2>>>();
        k_hist <<<(EE + 255) / 256, 256, 0, s2>>>(ei, ew, et);
        k_dinv <<<(NN + 255) / 256, 256, 0, s2>>>();
        k_scanA<<<SCAN_BLOCKS, 1024, 0, s2>>>();
        k_scanB<<<1, 128, 0, s2>>>();
        k_scanC<<<SCAN_BLOCKS, 1024, 0, s2>>>();
        k_fill <<<(EE + 255) / 256, 256, 0, s2>>>(ei, ew, et);
        cudaEventRecord(evJ, s2);

        k_gemm1<<<gemm_blocks, 256, smem1>>>(x, W1);
        cudaStreamWaitEvent(0, evJ, 0);
    } else {
        // serial fallback
        k_init <<<(NN + 255) / 256, 256>>>();
        k_hist <<<(EE + 255) / 256, 256>>>(ei, ew, et);
        k_dinv <<<(NN + 255) / 256, 256>>>();
        k_scanA<<<SCAN_BLOCKS, 1024>>>();
        k_scanB<<<1, 128>>>();
        k_scanC<<<SCAN_BLOCKS, 1024>>>();
        k_fill <<<(EE + 255) / 256, 256>>>(ei, ew, et);
        k_gemm1<<<gemm_blocks, 256, smem1>>>(x, W1);
    }

    // layer 1 aggregate
    k_gather1<<<NN * 32 / 256, 256>>>(b1, a1);

    // layer 2
    k_gemm2<<<gemm_blocks, 256, smem2>>>(W2);
    k_gather2<<<NN * 16 / 256, 256>>>(b2, a2);

    k_final<<<HALF * 16 / 256, 256>>>(out);
}

// round 6
// speedup vs baseline: 1.5950x; 1.0239x over previous
#include <cuda_runtime.h>
#include <cuda_fp16.h>

#define NN   100000
#define EE   1600000
#define HALF (NN/2)
#define SCAN_BLOCKS 98   // 98*1024 = 100352 >= NN

// ---------------- scratch (device globals; allocation-free) ----------------
__device__ float  g_xw[(size_t)NN * 128];   // x@W fp32 (self terms; layer2 uses first NN*64)
__device__ __half g_xwh[(size_t)NN * 128];  // fp16 copy for gather (layer2 uses first NN*64)
__device__ float  g_h[(size_t)NN * 128];    // layer-1 activations (fp32)
__device__ float  g_deg1[NN], g_deg2[NN], g_dinv1[NN], g_dinv2[NN];
__device__ int    g_hist[NN],  g_hist2[NN];
__device__ int    g_off[NN + 1], g_off2[NN + 1];
__device__ int    g_cur[NN],   g_cur2[NN];
__device__ int    g_bsum[SCAN_BLOCKS], g_bsum2[SCAN_BLOCKS];
__device__ int2   g_e1[EE];                 // (src, ew*dinv1[src]) grouped by dst
__device__ int2   g_e2[EE];                 // (src, et*dinv2[src]) grouped by dst, et>0 only

// ---------------- packed f32x2 helpers (sm_103a FFMA2) ----------------
__device__ __forceinline__ unsigned long long pack_dup(float a) {
    unsigned long long r;
    asm("mov.b64 %0, {%1, %1};" : "=l"(r) : "r"(__float_as_uint(a)));
    return r;
}
__device__ __forceinline__ unsigned long long pack2f(float2 v) {
    unsigned long long r;
    asm("mov.b64 %0, {%1, %2};" : "=l"(r) : "r"(__float_as_uint(v.x)), "r"(__float_as_uint(v.y)));
    return r;
}
__device__ __forceinline__ float2 unpack2(unsigned long long v) {
    unsigned int lo, hi;
    asm("mov.b64 {%0, %1}, %2;" : "=r"(lo), "=r"(hi) : "l"(v));
    return make_float2(__uint_as_float(lo), __uint_as_float(hi));
}
__device__ __forceinline__ void fma2(unsigned long long& d, unsigned long long a, unsigned long long b) {
    asm("fma.rn.f32x2 %0, %1, %2, %0;" : "+l"(d) : "l"(a), "l"(b));
}
__device__ __forceinline__ unsigned int h2_from_f2(float lo, float hi) {
    __half2 h = __floats2half2_rn(lo, hi);
    return *reinterpret_cast<unsigned int*>(&h);
}

// ---------------- CSR build ----------------
__global__ void k_init() {
    int i = blockIdx.x * 256 + threadIdx.x;
    if (i < NN) {
        g_hist[i] = 0; g_hist2[i] = 0;
        g_deg1[i] = 1.0f; g_deg2[i] = 1.0f;   // self-loop weight 1
    }
}
__global__ void k_hist(const int* __restrict__ ei, const float* __restrict__ w,
                       const int* __restrict__ et) {
    int e = blockIdx.x * 256 + threadIdx.x;
    if (e < EE) {
        int dst = ei[EE + e];
        int t = et[e];
        atomicAdd(&g_hist[dst], 1);
        if (t > 0) {
            atomicAdd(&g_hist2[dst], 1);
            atomicAdd(&g_deg2[dst], (float)t);
        }
        atomicAdd(&g_deg1[dst], w[e]);
    }
}
__global__ void k_dinv() {
    int i = blockIdx.x * 256 + threadIdx.x;
    if (i < NN) {
        float d1 = g_deg1[i], d2 = g_deg2[i];
        g_dinv1[i] = (d1 > 0.f) ? rsqrtf(d1) : 0.f;
        g_dinv2[i] = (d2 > 0.f) ? rsqrtf(d2) : 0.f;
    }
}

__device__ __forceinline__ int warp_incl_scan(int v, int lane) {
    int x = v;
#pragma unroll
    for (int o = 1; o < 32; o <<= 1) {
        int y = __shfl_up_sync(0xffffffffu, x, o);
        if (lane >= o) x += y;
    }
    return x;
}

// ---- scan phase 1 (both hist arrays) ----
__global__ void k_scanA() {
    __shared__ int wsum[32], wsum2[32];
    const int tid = threadIdx.x;
    const int lane = tid & 31, wid = tid >> 5;
    int i = blockIdx.x * 1024 + tid;
    int v1 = (i < NN) ? g_hist[i] : 0;
    int v2 = (i < NN) ? g_hist2[i] : 0;
    int x1 = warp_incl_scan(v1, lane);
    int x2 = warp_incl_scan(v2, lane);
    if (lane == 31) { wsum[wid] = x1; wsum2[wid] = x2; }
    __syncthreads();
    if (wid == 0) {
        int s1 = warp_incl_scan(wsum[lane], lane);
        int s2 = warp_incl_scan(wsum2[lane], lane);
        wsum[lane] = s1; wsum2[lane] = s2;
    }
    __syncthreads();
    int e1 = (x1 - v1) + ((wid > 0) ? wsum[wid - 1] : 0);
    int e2 = (x2 - v2) + ((wid > 0) ? wsum2[wid - 1] : 0);
    if (i < NN) { g_off[i] = e1; g_off2[i] = e2; }
    if (tid == 0) { g_bsum[blockIdx.x] = wsum[31]; g_bsum2[blockIdx.x] = wsum2[31]; }
}

// ---- scan phase 2 ----
__global__ void k_scanB() {
    __shared__ int ws[4], ws2[4];
    const int tid = threadIdx.x;                 // 128 threads
    const int lane = tid & 31, wid = tid >> 5;
    int v1 = (tid < SCAN_BLOCKS) ? g_bsum[tid] : 0;
    int v2 = (tid < SCAN_BLOCKS) ? g_bsum2[tid] : 0;
    int x1 = warp_incl_scan(v1, lane);
    int x2 = warp_incl_scan(v2, lane);
    if (lane == 31) { ws[wid] = x1; ws2[wid] = x2; }
    __syncthreads();
    int add1 = 0, add2 = 0;
#pragma unroll
    for (int w = 0; w < 4; w++) {
        add1 += (w < wid) ? ws[w] : 0;
        add2 += (w < wid) ? ws2[w] : 0;
    }
    if (tid < SCAN_BLOCKS) {
        g_bsum[tid]  = (x1 - v1) + add1;
        g_bsum2[tid] = (x2 - v2) + add2;
        if (tid == SCAN_BLOCKS - 1) {
            g_off[NN]  = x1 + add1;   // = EE
            g_off2[NN] = x2 + add2;   // = #nonzero-type edges
        }
    }
}

// ---- scan phase 3 ----
__global__ void k_scanC() {
    int i = blockIdx.x * 1024 + threadIdx.x;
    if (i < NN) {
        int o1 = g_off[i]  + g_bsum[i >> 10];
        int o2 = g_off2[i] + g_bsum2[i >> 10];
        g_off[i] = o1;  g_cur[i] = o1;
        g_off2[i] = o2; g_cur2[i] = o2;
    }
}

__global__ void k_fill(const int* __restrict__ ei, const float* __restrict__ w,
                       const int* __restrict__ et) {
    int e = blockIdx.x * 256 + threadIdx.x;
    if (e < EE) {
        int src = ei[e];
        int dst = ei[EE + e];
        int pos = atomicAdd(&g_cur[dst], 1);
        g_e1[pos] = make_int2(src, __float_as_int(w[e] * g_dinv1[src]));
        int t = et[e];
        if (t > 0) {
            int pos2 = atomicAdd(&g_cur2[dst], 1);
            g_e2[pos2] = make_int2(src, __float_as_int((float)t * g_dinv2[src]));
        }
    }
}

// ---------------- GEMM1: g_xw = x @ W1 (fp32) + fp16 copy ----------------
__global__ void k_gemm1(const float* __restrict__ x, const float* __restrict__ W) {
    extern __shared__ float sm[];
    float* Ws = sm;              // 128*128
    float* Xs = sm + 128 * 128;  // 128 * 66
    const int tid = threadIdx.x;
    const int rbase = blockIdx.x * 64;

    const float4* W4 = (const float4*)W;
    float4* Ws4 = (float4*)Ws;
#pragma unroll
    for (int i = 0; i < 16; i++) Ws4[i * 256 + tid] = W4[i * 256 + tid];

#pragma unroll
    for (int it = 0; it < 32; it++) {
        int idx = it * 256 + tid;
        int r = idx >> 7, k = idx & 127;
        int row = rbase + r;
        Xs[k * 66 + r] = (row < NN) ? x[(size_t)row * 128 + k] : 0.f;
    }
    __syncthreads();

    const int tx = tid & 31, ty = tid >> 5;
    const int cb = tx * 4, rb = ty * 8;
    unsigned long long acc[4][4];
#pragma unroll
    for (int p = 0; p < 4; p++)
#pragma unroll
        for (int c = 0; c < 4; c++) acc[p][c] = 0ull;

#pragma unroll 4
    for (int k = 0; k < 128; k++) {
        float4 w4 = *(const float4*)(Ws + k * 128 + cb);
        unsigned long long wd0 = pack_dup(w4.x), wd1 = pack_dup(w4.y),
                           wd2 = pack_dup(w4.z), wd3 = pack_dup(w4.w);
        const float* xrow = Xs + k * 66 + rb;
#pragma unroll
        for (int p = 0; p < 4; p++) {
            unsigned long long a2 = pack2f(*(const float2*)(xrow + 2 * p));
            fma2(acc[p][0], a2, wd0);
            fma2(acc[p][1], a2, wd1);
            fma2(acc[p][2], a2, wd2);
            fma2(acc[p][3], a2, wd3);
        }
    }

#pragma unroll
    for (int p = 0; p < 4; p++) {
        float2 c0 = unpack2(acc[p][0]), c1 = unpack2(acc[p][1]),
               c2 = unpack2(acc[p][2]), c3 = unpack2(acc[p][3]);
        int row0 = rbase + rb + 2 * p;
        if (row0 < NN) {
            float4 o = make_float4(c0.x, c1.x, c2.x, c3.x);
            *(float4*)&g_xw[(size_t)row0 * 128 + cb] = o;
            uint2 hv; hv.x = h2_from_f2(o.x, o.y); hv.y = h2_from_f2(o.z, o.w);
            *(uint2*)&g_xwh[(size_t)row0 * 128 + cb] = hv;
        }
        int row1 = row0 + 1;
        if (row1 < NN) {
            float4 o = make_float4(c0.y, c1.y, c2.y, c3.y);
            *(float4*)&g_xw[(size_t)row1 * 128 + cb] = o;
            uint2 hv; hv.x = h2_from_f2(o.x, o.y); hv.y = h2_from_f2(o.z, o.w);
            *(uint2*)&g_xwh[(size_t)row1 * 128 + cb] = hv;
        }
    }
}

// ---------------- GEMM2: g_xw[:,0:64] = h @ W2 (fp32) + fp16 copy ----------------
__global__ void k_gemm2(const float* __restrict__ W) {
    extern __shared__ float sm[];
    float* Ws = sm;              // 128*64
    float* Xs = sm + 128 * 64;   // 128 * 66
    const int tid = threadIdx.x;
    const int rbase = blockIdx.x * 64;

    const float4* W4 = (const float4*)W;
    float4* Ws4 = (float4*)Ws;
#pragma unroll
    for (int i = 0; i < 8; i++) Ws4[i * 256 + tid] = W4[i * 256 + tid];

#pragma unroll
    for (int it = 0; it < 32; it++) {
        int idx = it * 256 + tid;
        int r = idx >> 7, k = idx & 127;
        int row = rbase + r;
        Xs[k * 66 + r] = (row < NN) ? g_h[(size_t)row * 128 + k] : 0.f;
    }
    __syncthreads();

    const int tx = tid & 15, ty = tid >> 4;
    const int cb = tx * 4, rb = ty * 4;
    unsigned long long acc[2][4];
#pragma unroll
    for (int p = 0; p < 2; p++)
#pragma unroll
        for (int c = 0; c < 4; c++) acc[p][c] = 0ull;

#pragma unroll 4
    for (int k = 0; k < 128; k++) {
        float4 w4 = *(const float4*)(Ws + k * 64 + cb);
        unsigned long long wd0 = pack_dup(w4.x), wd1 = pack_dup(w4.y),
                           wd2 = pack_dup(w4.z), wd3 = pack_dup(w4.w);
        const float* xrow = Xs + k * 66 + rb;
#pragma unroll
        for (int p = 0; p < 2; p++) {
            unsigned long long a2 = pack2f(*(const float2*)(xrow + 2 * p));
            fma2(acc[p][0], a2, wd0);
            fma2(acc[p][1], a2, wd1);
            fma2(acc[p][2], a2, wd2);
            fma2(acc[p][3], a2, wd3);
        }
    }

#pragma unroll
    for (int p = 0; p < 2; p++) {
        float2 c0 = unpack2(acc[p][0]), c1 = unpack2(acc[p][1]),
               c2 = unpack2(acc[p][2]), c3 = unpack2(acc[p][3]);
        int row0 = rbase + rb + 2 * p;
        if (row0 < NN) {
            float4 o = make_float4(c0.x, c1.x, c2.x, c3.x);
            *(float4*)&g_xw[(size_t)row0 * 64 + cb] = o;
            uint2 hv; hv.x = h2_from_f2(o.x, o.y); hv.y = h2_from_f2(o.z, o.w);
            *(uint2*)&g_xwh[(size_t)row0 * 64 + cb] = hv;
        }
        int row1 = row0 + 1;
        if (row1 < NN) {
            float4 o = make_float4(c0.y, c1.y, c2.y, c3.y);
            *(float4*)&g_xw[(size_t)row1 * 64 + cb] = o;
            uint2 hv; hv.x = h2_from_f2(o.x, o.y); hv.y = h2_from_f2(o.z, o.w);
            *(uint2*)&g_xwh[(size_t)row1 * 64 + cb] = hv;
        }
    }
}

// ---------------- gather layer 1: warp per dst node, 128 ch; fp16 neighbors ----------------
__global__ void k_gather1(const float* __restrict__ b, const float* __restrict__ al) {
    int gid = blockIdx.x * 256 + threadIdx.x;   // NN*32 threads exactly
    int node = gid >> 5;
    int lane = gid & 31;
    int beg = g_off[node], end = g_off[node + 1];
    float s = g_dinv1[node];

    // self loop (fp32 exact): xw[node]*dinv^2; one factor here, one in epilogue
    float4 acc = *(const float4*)&g_xw[(size_t)node * 128 + lane * 4];
    acc.x *= s; acc.y *= s; acc.z *= s; acc.w *= s;

    int i = beg;
    for (; i + 1 < end; i += 2) {
        int2 e0 = g_e1[i];
        int2 e1 = g_e1[i + 1];
        uint2 u0 = *(const uint2*)&g_xwh[(size_t)e0.x * 128 + lane * 4];
        uint2 u1 = *(const uint2*)&g_xwh[(size_t)e1.x * 128 + lane * 4];
        float w0 = __int_as_float(e0.y), w1 = __int_as_float(e1.y);
        float2 a0 = __half22float2(*(__half2*)&u0.x);
        float2 b0 = __half22float2(*(__half2*)&u0.y);
        float2 a1 = __half22float2(*(__half2*)&u1.x);
        float2 b1 = __half22float2(*(__half2*)&u1.y);
        acc.x += w0 * a0.x + w1 * a1.x;
        acc.y += w0 * a0.y + w1 * a1.y;
        acc.z += w0 * b0.x + w1 * b1.x;
        acc.w += w0 * b0.y + w1 * b1.y;
    }
    if (i < end) {
        int2 e0 = g_e1[i];
        uint2 u0 = *(const uint2*)&g_xwh[(size_t)e0.x * 128 + lane * 4];
        float w0 = __int_as_float(e0.y);
        float2 a0 = __half22float2(*(__half2*)&u0.x);
        float2 b0 = __half22float2(*(__half2*)&u0.y);
        acc.x += w0 * a0.x; acc.y += w0 * a0.y;
        acc.z += w0 * b0.x; acc.w += w0 * b0.y;
    }

    float4 bb = *(const float4*)&b[lane * 4];
    float4 aa = *(const float4*)&al[lane * 4];
    acc.x = acc.x * s + bb.x; acc.y = acc.y * s + bb.y;
    acc.z = acc.z * s + bb.z; acc.w = acc.w * s + bb.w;
    acc.x = (acc.x >= 0.f) ? acc.x : aa.x * acc.x;
    acc.y = (acc.y >= 0.f) ? acc.y : aa.y * acc.y;
    acc.z = (acc.z >= 0.f) ? acc.z : aa.z * acc.z;
    acc.w = (acc.w >= 0.f) ? acc.w : aa.w * acc.w;
    *(float4*)&g_h[(size_t)node * 128 + lane * 4] = acc;
}

// ---------------- gather layer 2 fused with half-combine ----------------
// 16 lanes per node PAIR (i, i+HALF); writes out[i] directly.
__device__ __forceinline__ float4 gather2_node(int node, int l16) {
    int beg = g_off2[node], end = g_off2[node + 1];
    float s = g_dinv2[node];
    float4 acc = *(const float4*)&g_xw[(size_t)node * 64 + l16 * 4];
    acc.x *= s; acc.y *= s; acc.z *= s; acc.w *= s;

    int i = beg;
    for (; i + 1 < end; i += 2) {
        int2 e0 = g_e2[i];
        int2 e1 = g_e2[i + 1];
        uint2 u0 = *(const uint2*)&g_xwh[(size_t)e0.x * 64 + l16 * 4];
        uint2 u1 = *(const uint2*)&g_xwh[(size_t)e1.x * 64 + l16 * 4];
        float w0 = __int_as_float(e0.y), w1 = __int_as_float(e1.y);
        float2 a0 = __half22float2(*(__half2*)&u0.x);
        float2 b0 = __half22float2(*(__half2*)&u0.y);
        float2 a1 = __half22float2(*(__half2*)&u1.x);
        float2 b1 = __half22float2(*(__half2*)&u1.y);
        acc.x += w0 * a0.x + w1 * a1.x;
        acc.y += w0 * a0.y + w1 * a1.y;
        acc.z += w0 * b0.x + w1 * b1.x;
        acc.w += w0 * b0.y + w1 * b1.y;
    }
    if (i < end) {
        int2 e0 = g_e2[i];
        uint2 u0 = *(const uint2*)&g_xwh[(size_t)e0.x * 64 + l16 * 4];
        float w0 = __int_as_float(e0.y);
        float2 a0 = __half22float2(*(__half2*)&u0.x);
        float2 b0 = __half22float2(*(__half2*)&u0.y);
        acc.x += w0 * a0.x; acc.y += w0 * a0.y;
        acc.z += w0 * b0.x; acc.w += w0 * b0.y;
    }
    acc.x *= s; acc.y *= s; acc.z *= s; acc.w *= s;
    return acc;
}

__global__ void k_gather2(const float* __restrict__ b, const float* __restrict__ al,
                          float* __restrict__ out) {
    int gid = blockIdx.x * 256 + threadIdx.x;   // HALF*16 threads exactly
    int i = gid >> 4;
    int l16 = gid & 15;

    float4 va = gather2_node(i, l16);
    float4 vb = gather2_node(i + HALF, l16);

    float4 bb = *(const float4*)&b[l16 * 4];
    float4 aa = *(const float4*)&al[l16 * 4];
    va.x += bb.x; va.y += bb.y; va.z += bb.z; va.w += bb.w;
    vb.x += bb.x; vb.y += bb.y; vb.z += bb.z; vb.w += bb.w;
    va.x = (va.x >= 0.f) ? va.x : aa.x * va.x;
    va.y = (va.y >= 0.f) ? va.y : aa.y * va.y;
    va.z = (va.z >= 0.f) ? va.z : aa.z * va.z;
    va.w = (va.w >= 0.f) ? va.w : aa.w * va.w;
    vb.x = (vb.x >= 0.f) ? vb.x : aa.x * vb.x;
    vb.y = (vb.y >= 0.f) ? vb.y : aa.y * vb.y;
    vb.z = (vb.z >= 0.f) ? vb.z : aa.z * vb.z;
    vb.w = (vb.w >= 0.f) ? vb.w : aa.w * vb.w;

    *(float4*)&out[(size_t)i * 64 + l16 * 4] =
        make_float4(0.5f * (va.x + vb.x), 0.5f * (va.y + vb.y),
                    0.5f * (va.z + vb.z), 0.5f * (va.w + vb.w));
}

// ---------------- launch ----------------
extern "C" void kernel_launch(void* const* d_in, const int* in_sizes, int n_in,
                              void* d_out, int out_size) {
    (void)in_sizes; (void)n_in; (void)out_size;
    const float* x   = (const float*)d_in[0];
    const int*   ei  = (const int*)d_in[1];
    const float* ew  = (const float*)d_in[2];
    const int*   et  = (const int*)d_in[3];
    const float* W1  = (const float*)d_in[4];
    const float* b1  = (const float*)d_in[5];
    const float* a1  = (const float*)d_in[6];
    const float* W2  = (const float*)d_in[7];
    const float* b2  = (const float*)d_in[8];
    const float* a2  = (const float*)d_in[9];
    float* out = (float*)d_out;

    const int smem1 = (128 * 128 + 128 * 66) * sizeof(float);
    const int smem2 = (128 * 64  + 128 * 66) * sizeof(float);
    cudaFuncSetAttribute(k_gemm1, cudaFuncAttributeMaxDynamicSharedMemorySize, smem1);
    cudaFuncSetAttribute(k_gemm2, cudaFuncAttributeMaxDynamicSharedMemorySize, smem2);

    const int gemm_blocks = (NN + 63) / 64;

    static cudaStream_t s2 = nullptr;
    static cudaEvent_t evF = nullptr, evJ = nullptr;
    static bool tried = false;
    if (!tried) {
        tried = true;
        if (cudaStreamCreateWithFlags(&s2, cudaStreamNonBlocking) != cudaSuccess) s2 = nullptr;
        if (s2) {
            if (cudaEventCreateWithFlags(&evF, cudaEventDisableTiming) != cudaSuccess) { s2 = nullptr; }
            else if (cudaEventCreateWithFlags(&evJ, cudaEventDisableTiming) != cudaSuccess) { s2 = nullptr; }
        }
    }

    if (s2) {
        cudaEventRecord(evF, 0);
        cudaStreamWaitEvent(s2, evF, 0);
        k_init <<<(NN + 255) / 256, 256, 0, s2>>>();
        k_hist <<<(EE + 255) / 256, 256, 0, s2>>>(ei, ew, et);
        k_dinv <<<(NN + 255) / 256, 256, 0, s2>>>();
        k_scanA<<<SCAN_BLOCKS, 1024, 0, s2>>>();
        k_scanB<<<1, 128, 0, s2>>>();
        k_scanC<<<SCAN_BLOCKS, 1024, 0, s2>>>();
        k_fill <<<(EE + 255) / 256, 256, 0, s2>>>(ei, ew, et);
        cudaEventRecord(evJ, s2);

        k_gemm1<<<gemm_blocks, 256, smem1>>>(x, W1);
        cudaStreamWaitEvent(0, evJ, 0);
    } else {
        k_init <<<(NN + 255) / 256, 256>>>();
        k_hist <<<(EE + 255) / 256, 256>>>(ei, ew, et);
        k_dinv <<<(NN + 255) / 256, 256>>>();
        k_scanA<<<SCAN_BLOCKS, 1024>>>();
        k_scanB<<<1, 128>>>();
        k_scanC<<<SCAN_BLOCKS, 1024>>>();
        k_fill <<<(EE + 255) / 256, 256>>>(ei, ew, et);
        k_gemm1<<<gemm_blocks, 256, smem1>>>(x, W1);
    }

    // layer 1 aggregate
    k_gather1<<<NN * 32 / 256, 256>>>(b1, a1);

    // layer 2 (+ fused half-combine)
    k_gemm2<<<gemm_blocks, 256, smem2>>>(W2);
    k_gather2<<<HALF * 16 / 256, 256>>>(b2, a2, out);
}